// round 2
// baseline (speedup 1.0000x reference)
#include <cuda_runtime.h>

// ---------------------------------------------------------------------------
// TensoRF slim renderer.
//   1) Transpose planes/lines from [3,C,H,W] -> [3,H*W,C] (channel-last) so
//      each bilinear corner is a contiguous vectorized load (float4s).
//   2) One block per ray (Ns threads); fused sigma+rgb, smem product scan
//      for transmittance, tree reduction for rgb.
//   Numerics: alpha computed via -expm1f(-x) (1-exp(-x) is catastrophically
//   cancelling for tiny sigma and dominated the rel_err in R1).
// ---------------------------------------------------------------------------

#define MAXG 320

__device__ float4 g_dplaneT[3][MAXG * MAXG * 2];  // 8 ch  = 2 float4 / texel
__device__ float4 g_aplaneT[3][MAXG * MAXG * 6];  // 24 ch = 6 float4 / texel
__device__ float4 g_dlineT[3][MAXG * 2];
__device__ float4 g_alineT[3][MAXG * 6];

__device__ __forceinline__ float* dst_for(int which) {
    switch (which) {
        case 0:  return (float*)g_dplaneT;
        case 1:  return (float*)g_aplaneT;
        case 2:  return (float*)g_dlineT;
        default: return (float*)g_alineT;
    }
}

// [3, C, HW] -> [3, HW, C]  (tiled through smem: coalesced on both sides)
__global__ void transpose_kernel(const float* __restrict__ in, int which,
                                 int C, int HW, int planeStride) {
    __shared__ float tile[24 * 128];
    int ntiles = (HW + 127) >> 7;
    int i  = blockIdx.x / ntiles;
    int t  = blockIdx.x - i * ntiles;
    int p0 = t << 7;
    int np = min(128, HW - p0);
    const float* src = in + (size_t)i * C * HW;
    float* dst = dst_for(which) + (size_t)i * planeStride + (size_t)p0 * C;

    for (int l = threadIdx.x; l < C * 128; l += blockDim.x) {
        int ch = l >> 7, pp = l & 127;
        if (pp < np) tile[l] = src[ch * HW + p0 + pp];
    }
    __syncthreads();
    for (int l = threadIdx.x; l < np * C; l += blockDim.x) {
        int pp = l / C, ch = l - pp * C;
        dst[l] = tile[(ch << 7) + pp];
    }
}

struct S1D { int i0, i1; float w; };

__device__ __forceinline__ S1D samp1d(float c, int G) {
    float f  = (c + 1.0f) * 0.5f * (float)(G - 1);
    float ff = floorf(f);
    S1D r;
    r.w = f - ff;                 // fractional part from UNclipped floor (matches ref)
    int i0 = (int)ff;
    i0 = min(max(i0, 0), G - 1);
    r.i0 = i0;
    r.i1 = min(i0 + 1, G - 1);
    return r;
}

__device__ __forceinline__ float4 bil4(float4 a, float4 b, float4 c, float4 d,
                                       float w00, float w01, float w10, float w11) {
    float4 o;
    o.x = a.x * w00 + b.x * w01 + c.x * w10 + d.x * w11;
    o.y = a.y * w00 + b.y * w01 + c.y * w10 + d.y * w11;
    o.z = a.z * w00 + b.z * w01 + c.z * w10 + d.z * w11;
    o.w = a.w * w00 + b.w * w01 + c.w * w10 + d.w * w11;
    return o;
}

__device__ __forceinline__ float4 lerp4(float4 a, float4 b, float w0, float w1) {
    float4 o;
    o.x = a.x * w0 + b.x * w1;
    o.y = a.y * w0 + b.y * w1;
    o.z = a.z * w0 + b.z * w1;
    o.w = a.w * w0 + b.w * w1;
    return o;
}

__global__ void render_kernel(const float* __restrict__ xyz,
                              const float* __restrict__ zvals,
                              const float* __restrict__ denw,
                              const float* __restrict__ appw,
                              const float* __restrict__ aabb,
                              float* __restrict__ out,
                              int Ns, int G) {
    extern __shared__ float sh[];
    float* s_z = sh;            // Ns
    float* s_A = sh + Ns;       // Ns (scan/reduce buffer)
    float* s_B = sh + 2 * Ns;   // Ns (scan double buffer)
    __shared__ float s_denw[24];
    __shared__ float s_appw[216];
    __shared__ float s_aabb[6];

    int r = blockIdx.x;
    int s = threadIdx.x;

    for (int l = s; l < 24;  l += Ns) s_denw[l] = denw[l];
    for (int l = s; l < 216; l += Ns) s_appw[l] = appw[l];
    for (int l = s; l < 6;   l += Ns) s_aabb[l] = aabb[l];
    s_z[s] = zvals[(size_t)r * Ns + s];
    __syncthreads();

    // normalized coords in [-1,1]
    size_t pidx = (size_t)(r * Ns + s) * 3;
    float nc[3];
#pragma unroll
    for (int k = 0; k < 3; k++) {
        float v = __ldg(&xyz[pidx + k]);
        nc[k] = (v - s_aabb[k]) * (2.0f / (s_aabb[3 + k] - s_aabb[k])) - 1.0f;
    }

    const int MA[3] = {0, 0, 1}, MB[3] = {1, 2, 2}, MV[3] = {2, 1, 0};

    float sig = 0.0f;
    float r0 = 0.0f, r1 = 0.0f, r2 = 0.0f;

#pragma unroll
    for (int i = 0; i < 3; i++) {
        S1D sx = samp1d(nc[MA[i]], G);
        S1D sy = samp1d(nc[MB[i]], G);
        S1D st = samp1d(nc[MV[i]], G);
        float w00 = (1.0f - sx.w) * (1.0f - sy.w);
        float w01 = sx.w * (1.0f - sy.w);
        float w10 = (1.0f - sx.w) * sy.w;
        float w11 = sx.w * sy.w;
        float lw0 = 1.0f - st.w, lw1 = st.w;
        int o00 = sy.i0 * G + sx.i0;
        int o01 = sy.i0 * G + sx.i1;
        int o10 = sy.i1 * G + sx.i0;
        int o11 = sy.i1 * G + sx.i1;

        // ---- density plane (8 ch) ----
        {
            const float4* pl = g_dplaneT[i];
            const float4* ln = g_dlineT[i];
#pragma unroll
            for (int k = 0; k < 2; k++) {
                float4 pf = bil4(pl[o00 * 2 + k], pl[o01 * 2 + k],
                                 pl[o10 * 2 + k], pl[o11 * 2 + k],
                                 w00, w01, w10, w11);
                float4 lf = lerp4(ln[st.i0 * 2 + k], ln[st.i1 * 2 + k], lw0, lw1);
                const float* wv = &s_denw[i * 8 + k * 4];
                sig += wv[0] * pf.x * lf.x + wv[1] * pf.y * lf.y
                     + wv[2] * pf.z * lf.z + wv[3] * pf.w * lf.w;
            }
        }
        // ---- appearance plane (24 ch) ----
        {
            const float4* pl = g_aplaneT[i];
            const float4* ln = g_alineT[i];
#pragma unroll
            for (int k = 0; k < 6; k++) {
                float4 pf = bil4(pl[o00 * 6 + k], pl[o01 * 6 + k],
                                 pl[o10 * 6 + k], pl[o11 * 6 + k],
                                 w00, w01, w10, w11);
                float4 lf = lerp4(ln[st.i0 * 6 + k], ln[st.i1 * 6 + k], lw0, lw1);
                float fx = pf.x * lf.x, fy = pf.y * lf.y;
                float fz = pf.z * lf.z, fw = pf.w * lf.w;
                int j = i * 24 + k * 4;
                r0 += s_appw[j]       * fx + s_appw[j + 1]       * fy
                    + s_appw[j + 2]   * fz + s_appw[j + 3]       * fw;
                r1 += s_appw[72 + j]  * fx + s_appw[72 + j + 1]  * fy
                    + s_appw[72 + j + 2] * fz + s_appw[72 + j + 3] * fw;
                r2 += s_appw[144 + j] * fx + s_appw[144 + j + 1] * fy
                    + s_appw[144 + j + 2] * fz + s_appw[144 + j + 3] * fw;
            }
        }
    }

    // sigma = softplus(feat - 10)
    float sfeat = sig - 10.0f;
    float sigma = (sfeat > 15.0f) ? sfeat : log1pf(expf(sfeat));

    float dist = (s < Ns - 1) ? (s_z[s + 1] - s_z[s]) : (s_z[Ns - 1] - s_z[Ns - 2]);
    // alpha = 1 - exp(-x): catastrophic cancellation for tiny x. expm1 keeps
    // the rounding error relative to alpha itself (~1e-7) instead of ~ulp(1)/x.
    float x = sigma * (dist * 25.0f);
    float alpha = -expm1f(-x);

    // exclusive product scan of (1 - alpha + 1e-10) -> transmittance
    float tp = 1.0f - alpha + 1e-10f;
    s_A[s] = tp;
    __syncthreads();
    float* cur = s_A;
    float* nxt = s_B;
    for (int off = 1; off < Ns; off <<= 1) {
        float v = cur[s];
        if (s >= off) v *= cur[s - off];
        nxt[s] = v;
        __syncthreads();
        float* tmp = cur; cur = nxt; nxt = tmp;
    }
    float T = (s == 0) ? 1.0f : cur[s - 1];
    float w = alpha * T;
    __syncthreads();

    // weighted rgb reduction over samples
    int npow = 1;
    while (npow < Ns) npow <<= 1;
    float vals[3] = {w * r0, w * r1, w * r2};
#pragma unroll
    for (int c = 0; c < 3; c++) {
        s_A[s] = vals[c];
        __syncthreads();
        for (int off = npow >> 1; off > 0; off >>= 1) {
            if (s < off && s + off < Ns) s_A[s] += s_A[s + off];
            __syncthreads();
        }
        if (s == 0) out[r * 3 + c] = s_A[0];
        __syncthreads();
    }
}

extern "C" void kernel_launch(void* const* d_in, const int* in_sizes, int n_in,
                              void* d_out, int out_size) {
    const float* xyz   = (const float*)d_in[0];
    const float* zvals = (const float*)d_in[2];
    const float* dp    = (const float*)d_in[3];
    const float* dl    = (const float*)d_in[4];
    const float* ap    = (const float*)d_in[5];
    const float* al    = (const float*)d_in[6];
    const float* denw  = (const float*)d_in[7];
    const float* appw  = (const float*)d_in[8];
    const float* aabb  = (const float*)d_in[9];

    int Nr = in_sizes[1] / 3;          // viewdirs (Nr,3)
    int Ns = in_sizes[2] / Nr;         // z_vals (Nr,Ns)
    int G  = in_sizes[4] / 24;         // density_lines (3,8,G)
    int HW = G * G;

    int ntp = (HW + 127) / 128;
    transpose_kernel<<<3 * ntp, 256>>>(dp, 0, 8,  HW, MAXG * MAXG * 8);
    transpose_kernel<<<3 * ntp, 256>>>(ap, 1, 24, HW, MAXG * MAXG * 24);
    int ntl = (G + 127) / 128;
    transpose_kernel<<<3 * ntl, 256>>>(dl, 2, 8,  G, MAXG * 8);
    transpose_kernel<<<3 * ntl, 256>>>(al, 3, 24, G, MAXG * 24);

    size_t shmem = (size_t)3 * Ns * sizeof(float);
    render_kernel<<<Nr, Ns, shmem>>>(xyz, zvals, denw, appw, aabb,
                                     (float*)d_out, Ns, G);
}

// round 3
// speedup vs baseline: 1.1703x; 1.1703x over previous
#include <cuda_runtime.h>

// ---------------------------------------------------------------------------
// TensoRF slim renderer, v3.
//  Prep (1 kernel): build combined 128B texels  g_tex[i][HW][32ch]
//    (ch0-7 density, ch8-31 appearance) and g_ltex[i][G][32ch] with the
//    density basis weights folded into the density line channels.
//  Render (1 kernel, block=ray, 256 thr):
//    Phase A: sigma per sample, warp-cooperative loads (4 pts/warp,
//             lane = pt*8 + corner*2 + half), octet shuffle-reduce.
//    Phase B: alpha (-expm1), smem product scan -> per-sample weights.
//    Phase C: weighted app-feature accumulation per lane across samples;
//             basis matvec applied ONCE per ray at the end (order swap).
// ---------------------------------------------------------------------------

#define MAXG  320
#define MAXHW (MAXG * MAXG)

__device__ float4 g_tex[3ull * MAXHW * 8];   // [i][p][8 float4]  ~39.3 MB
__device__ float4 g_ltex[3 * MAXG * 8];      // [i][g][8 float4]

// ---------------- prep: interleave channels into 128B texels ----------------
__global__ void prep_kernel(const float* __restrict__ dp, const float* __restrict__ ap,
                            const float* __restrict__ dl, const float* __restrict__ al,
                            const float* __restrict__ denw, int G) {
    __shared__ float tile[32][129];
    int HW  = G * G;
    int ntp = (HW + 127) >> 7;
    int ntl = (G + 127) >> 7;
    int b = blockIdx.x;
    if (b < 3 * ntp) {
        int i = b / ntp, t = b - i * ntp;
        int p0 = t << 7;
        int np = min(128, HW - p0);
        for (int idx = threadIdx.x; idx < 32 * 128; idx += blockDim.x) {
            int ch = idx >> 7, p = idx & 127;
            float v = 0.f;
            if (p < np)
                v = (ch < 8) ? dp[(size_t)(i * 8 + ch) * HW + p0 + p]
                             : ap[(size_t)(i * 24 + ch - 8) * HW + p0 + p];
            tile[ch][p] = v;
        }
        __syncthreads();
        float* dst = (float*)(g_tex + ((size_t)i * MAXHW + p0) * 8);
        for (int idx = threadIdx.x; idx < np * 32; idx += blockDim.x) {
            int p = idx >> 5, ch = idx & 31;
            dst[idx] = tile[ch][p];
        }
    } else {
        b -= 3 * ntp;
        int i = b / ntl, t = b - i * ntl;
        int g0 = t << 7;
        int ng = min(128, G - g0);
        for (int idx = threadIdx.x; idx < 32 * 128; idx += blockDim.x) {
            int ch = idx >> 7, g = idx & 127;
            float v = 0.f;
            if (g < ng) {
                if (ch < 8) v = dl[(i * 8 + ch) * G + g0 + g] * denw[i * 8 + ch];
                else        v = al[(i * 24 + ch - 8) * G + g0 + g];
            }
            tile[ch][g] = v;
        }
        __syncthreads();
        float* dst = (float*)(g_ltex + ((size_t)i * MAXG + g0) * 8);
        for (int idx = threadIdx.x; idx < ng * 32; idx += blockDim.x) {
            int g = idx >> 5, ch = idx & 31;
            dst[idx] = tile[ch][g];
        }
    }
}

// ---------------- render ----------------
struct S1D { int i0, i1; float w; };

__device__ __forceinline__ S1D samp1d(float c, int G) {
    float f  = (c + 1.0f) * 0.5f * (float)(G - 1);
    float ff = floorf(f);
    S1D r;
    r.w = f - ff;
    int i0 = (int)ff;
    i0 = min(max(i0, 0), G - 1);
    r.i0 = i0;
    r.i1 = min(i0 + 1, G - 1);
    return r;
}

__device__ __forceinline__ float4 xor2_add(float4 v) {
    v.x += __shfl_xor_sync(0xffffffffu, v.x, 2);
    v.y += __shfl_xor_sync(0xffffffffu, v.y, 2);
    v.z += __shfl_xor_sync(0xffffffffu, v.z, 2);
    v.w += __shfl_xor_sync(0xffffffffu, v.w, 2);
    return v;
}

__device__ __forceinline__ float4 scale4(float4 v, float s) {
    v.x *= s; v.y *= s; v.z *= s; v.w *= s;
    return v;
}

__global__ __launch_bounds__(256)
void render_kernel(const float* __restrict__ xyz,
                   const float* __restrict__ zvals,
                   const float* __restrict__ appw,
                   const float* __restrict__ aabb,
                   float* __restrict__ out,
                   int Ns, int G) {
    __shared__ float s_nc[256 * 3];
    __shared__ float s_z[256];
    __shared__ float s_sig[256];
    __shared__ float s_A[256];
    __shared__ float s_B[256];
    __shared__ float s_w[256];
    __shared__ float s_appw[216];
    __shared__ float s_part[8 * 3];

    const int r = blockIdx.x;
    const int s = threadIdx.x;
    const int o = s & 31;            // lane
    const int wrp = s >> 5;          // warp id
    const int t = o >> 3;            // octet (point within quad)
    const int c = (o >> 1) & 3;      // corner (bit0 -> x / line tap, bit1 -> y)
    const int h = o & 1;             // half (which channel group)

    for (int l = s; l < 216; l += blockDim.x) s_appw[l] = appw[l];
    {
        size_t base = ((size_t)r * Ns + s) * 3;
#pragma unroll
        for (int k = 0; k < 3; k++) {
            float lo = aabb[k], hi = aabb[3 + k];
            float v = xyz[base + k];
            s_nc[s * 3 + k] = (v - lo) * (2.0f / (hi - lo)) - 1.0f;
        }
        s_z[s] = zvals[(size_t)r * Ns + s];
    }
    __syncthreads();

    const int MA[3] = {0, 0, 1}, MB[3] = {1, 2, 2}, MV[3] = {2, 1, 0};

    // ---------- Phase A: sigma features ----------
    for (int it = 0; it < 8; it++) {
        int p  = (wrp << 5) + (it << 2) + t;
        int p3 = p * 3;
        float sig = 0.f;
#pragma unroll
        for (int i = 0; i < 3; i++) {
            S1D sx = samp1d(s_nc[p3 + MA[i]], G);
            S1D sy = samp1d(s_nc[p3 + MB[i]], G);
            S1D st = samp1d(s_nc[p3 + MV[i]], G);
            int   xo = (c & 1) ? sx.i1 : sx.i0;
            int   yo = (c & 2) ? sy.i1 : sy.i0;
            float wc = ((c & 1) ? sx.w : 1.f - sx.w) * ((c & 2) ? sy.w : 1.f - sy.w);
            const float4* tex = g_tex + ((size_t)i * MAXHW + (size_t)(yo * G + xo)) * 8;
            float4 val = tex[h];                       // density f4 (h = 0/1)
            int   tap = (c & 1) ? st.i1 : st.i0;
            float lw  = (c & 1) ? st.w  : 1.f - st.w;
            const float4* lt = g_ltex + ((size_t)i * MAXG + tap) * 8;
            float4 lv = xor2_add(scale4(lt[h], lw));   // lerped line (denw folded)
            sig += wc * (val.x * lv.x + val.y * lv.y + val.z * lv.z + val.w * lv.w);
        }
        sig += __shfl_xor_sync(0xffffffffu, sig, 1);
        sig += __shfl_xor_sync(0xffffffffu, sig, 2);
        sig += __shfl_xor_sync(0xffffffffu, sig, 4);
        if ((o & 7) == 0) s_sig[p] = sig;
    }
    __syncthreads();

    // ---------- Phase B: alpha + transmittance scan -> weights ----------
    {
        float sfeat = s_sig[s] - 10.0f;
        float sigma = (sfeat > 15.0f) ? sfeat : log1pf(expf(sfeat));
        float dist  = (s < Ns - 1) ? (s_z[s + 1] - s_z[s]) : (s_z[Ns - 1] - s_z[Ns - 2]);
        float alpha = -expm1f(-sigma * (dist * 25.0f));
        s_A[s] = 1.0f - alpha + 1e-10f;
        __syncthreads();
        float* cur = s_A;
        float* nxt = s_B;
        for (int off = 1; off < Ns; off <<= 1) {
            float v = cur[s];
            if (s >= off) v *= cur[s - off];
            nxt[s] = v;
            __syncthreads();
            float* tmp = cur; cur = nxt; nxt = tmp;
        }
        float T = (s == 0) ? 1.0f : cur[s - 1];
        s_w[s] = alpha * T;
    }
    __syncthreads();

    // ---------- Phase C: weighted appearance-feature accumulation ----------
    float4 acc[9];
#pragma unroll
    for (int j = 0; j < 9; j++) acc[j] = make_float4(0.f, 0.f, 0.f, 0.f);

    for (int it = 0; it < 8; it++) {
        int p  = (wrp << 5) + (it << 2) + t;
        int p3 = p * 3;
        float wp = s_w[p];
#pragma unroll
        for (int i = 0; i < 3; i++) {
            S1D sx = samp1d(s_nc[p3 + MA[i]], G);
            S1D sy = samp1d(s_nc[p3 + MB[i]], G);
            S1D st = samp1d(s_nc[p3 + MV[i]], G);
            int   xo = (c & 1) ? sx.i1 : sx.i0;
            int   yo = (c & 2) ? sy.i1 : sy.i0;
            float wc = ((c & 1) ? sx.w : 1.f - sx.w) * ((c & 2) ? sy.w : 1.f - sy.w);
            const float4* tex = g_tex + ((size_t)i * MAXHW + (size_t)(yo * G + xo)) * 8
                                + 2 + h * 3;
            float4 v0 = tex[0];
            float4 v1 = tex[1];
            float4 v2 = tex[2];
            int   tap = (c & 1) ? st.i1 : st.i0;
            float lw  = (c & 1) ? st.w  : 1.f - st.w;
            const float4* lt = g_ltex + ((size_t)i * MAXG + tap) * 8 + 2 + h * 3;
            float4 l0 = xor2_add(scale4(lt[0], lw));
            float4 l1 = xor2_add(scale4(lt[1], lw));
            float4 l2 = xor2_add(scale4(lt[2], lw));
            float wcw = wc * wp;
            acc[i * 3 + 0].x = fmaf(v0.x, wcw * l0.x, acc[i * 3 + 0].x);
            acc[i * 3 + 0].y = fmaf(v0.y, wcw * l0.y, acc[i * 3 + 0].y);
            acc[i * 3 + 0].z = fmaf(v0.z, wcw * l0.z, acc[i * 3 + 0].z);
            acc[i * 3 + 0].w = fmaf(v0.w, wcw * l0.w, acc[i * 3 + 0].w);
            acc[i * 3 + 1].x = fmaf(v1.x, wcw * l1.x, acc[i * 3 + 1].x);
            acc[i * 3 + 1].y = fmaf(v1.y, wcw * l1.y, acc[i * 3 + 1].y);
            acc[i * 3 + 1].z = fmaf(v1.z, wcw * l1.z, acc[i * 3 + 1].z);
            acc[i * 3 + 1].w = fmaf(v1.w, wcw * l1.w, acc[i * 3 + 1].w);
            acc[i * 3 + 2].x = fmaf(v2.x, wcw * l2.x, acc[i * 3 + 2].x);
            acc[i * 3 + 2].y = fmaf(v2.y, wcw * l2.y, acc[i * 3 + 2].y);
            acc[i * 3 + 2].z = fmaf(v2.z, wcw * l2.z, acc[i * 3 + 2].z);
            acc[i * 3 + 2].w = fmaf(v2.w, wcw * l2.w, acc[i * 3 + 2].w);
        }
    }

    // reduce acc across corners (xor 2,4) and octets/points (xor 8,16)
#pragma unroll
    for (int j = 0; j < 9; j++) {
#pragma unroll
        for (int m = 2; m <= 16; m <<= 1) {
            acc[j].x += __shfl_xor_sync(0xffffffffu, acc[j].x, m);
            acc[j].y += __shfl_xor_sync(0xffffffffu, acc[j].y, m);
            acc[j].z += __shfl_xor_sync(0xffffffffu, acc[j].z, m);
            acc[j].w += __shfl_xor_sync(0xffffffffu, acc[j].w, m);
        }
    }

    // per-warp basis matvec (each lane: its h's channels), combine h via xor1
    float q0 = 0.f, q1 = 0.f, q2 = 0.f;
#pragma unroll
    for (int i = 0; i < 3; i++) {
#pragma unroll
        for (int k = 0; k < 3; k++) {
            int chb = (h * 3 + k) * 4;
            float4 a = acc[i * 3 + k];
            const float* w0 = &s_appw[0 * 72 + i * 24 + chb];
            const float* w1 = &s_appw[1 * 72 + i * 24 + chb];
            const float* w2 = &s_appw[2 * 72 + i * 24 + chb];
            q0 += a.x * w0[0] + a.y * w0[1] + a.z * w0[2] + a.w * w0[3];
            q1 += a.x * w1[0] + a.y * w1[1] + a.z * w1[2] + a.w * w1[3];
            q2 += a.x * w2[0] + a.y * w2[1] + a.z * w2[2] + a.w * w2[3];
        }
    }
    q0 += __shfl_xor_sync(0xffffffffu, q0, 1);
    q1 += __shfl_xor_sync(0xffffffffu, q1, 1);
    q2 += __shfl_xor_sync(0xffffffffu, q2, 1);
    if (o == 0) {
        s_part[wrp * 3 + 0] = q0;
        s_part[wrp * 3 + 1] = q1;
        s_part[wrp * 3 + 2] = q2;
    }
    __syncthreads();
    if (s < 3) {
        float sum = 0.f;
        int nw = blockDim.x >> 5;
        for (int ww = 0; ww < nw; ww++) sum += s_part[ww * 3 + s];
        out[r * 3 + s] = sum;
    }
}

extern "C" void kernel_launch(void* const* d_in, const int* in_sizes, int n_in,
                              void* d_out, int out_size) {
    const float* xyz   = (const float*)d_in[0];
    const float* zvals = (const float*)d_in[2];
    const float* dp    = (const float*)d_in[3];
    const float* dl    = (const float*)d_in[4];
    const float* ap    = (const float*)d_in[5];
    const float* al    = (const float*)d_in[6];
    const float* denw  = (const float*)d_in[7];
    const float* appw  = (const float*)d_in[8];
    const float* aabb  = (const float*)d_in[9];

    int Nr = in_sizes[1] / 3;
    int Ns = in_sizes[2] / Nr;
    int G  = in_sizes[4] / 24;
    int HW = G * G;

    int ntp = (HW + 127) / 128;
    int ntl = (G + 127) / 128;
    prep_kernel<<<3 * ntp + 3 * ntl, 256>>>(dp, ap, dl, al, denw, G);
    render_kernel<<<Nr, Ns>>>(xyz, zvals, appw, aabb, (float*)d_out, Ns, G);
}